// round 2
// baseline (speedup 1.0000x reference)
#include <cuda_runtime.h>

#define NUM_C 19
#define HW (512 * 512)
#define BATCH 8
#define NPIX (BATCH * HW)
#define IGNORE_IDX 255
// -log(1e-6)
#define NLL_CLAMP 13.815510557964274f

// Global scratch accumulators (device globals: allocation-free).
__device__ double g_csum[NUM_C];
__device__ unsigned long long g_ccnt[NUM_C];
__device__ double g_ce;
__device__ unsigned long long g_nv;

__global__ void cepf_init_kernel() {
    int i = threadIdx.x;
    if (i < NUM_C) {
        g_csum[i] = 0.0;
        g_ccnt[i] = 0ULL;
    }
    if (i == 0) {
        g_ce = 0.0;
        g_nv = 0ULL;
    }
}

// Process one pixel's 19 logits (already in registers, compile-time indexed).
__device__ __forceinline__ void process_pixel(
    const float x[NUM_C], int t,
    float& ce_local, unsigned& nv_local,
    float* s_sum, unsigned* s_cnt)
{
    bool valid = (t != IGNORE_IDX);
    int tc = t;
    if (tc < 0) tc = 0;
    if (tc > NUM_C - 1) tc = NUM_C - 1;

    float m = -3.402823466e38f;
    float xt = 0.f;
#pragma unroll
    for (int c = 0; c < NUM_C; c++) {
        m = fmaxf(m, x[c]);
        if (c == tc) xt = x[c];
    }
    float se = 0.f;
#pragma unroll
    for (int c = 0; c < NUM_C; c++) {
        se += __expf(x[c] - m);
    }
    float logZ = m + __logf(se);
    float nll = logZ - xt;

    if (valid) {
        ce_local += nll;
        nv_local += 1u;
        // pt = clip(exp(-nll), 1e-6, 1)  =>  -log(pt) = clamp(nll, 0, 13.8155)
        float lg = fminf(fmaxf(nll, 0.f), NLL_CLAMP);
        float pt = __expf(-lg);
        float om = 1.f - pt;
        float focal = lg * om * om * om;
        atomicAdd(&s_sum[tc], focal);
        atomicAdd(&s_cnt[tc], 1u);
    }
}

__global__ __launch_bounds__(256) void cepf_main_kernel(
    const float* __restrict__ logits,
    const int* __restrict__ targets)
{
    __shared__ float s_sum[NUM_C];
    __shared__ unsigned s_cnt[NUM_C];
    __shared__ float s_ce;
    __shared__ unsigned s_nv;

    int tid = threadIdx.x;
    if (tid < NUM_C) {
        s_sum[tid] = 0.f;
        s_cnt[tid] = 0u;
    }
    if (tid == 0) {
        s_ce = 0.f;
        s_nv = 0u;
    }
    __syncthreads();

    // Each thread handles 4 consecutive pixels (one float4 per class).
    long long g = (long long)blockIdx.x * blockDim.x + tid;
    long long p = g * 4;  // pixel base; multiple of 4, HW multiple of 4 => same batch b for all 4
    int b = (int)(p >> 18);            // p / HW
    int hw = (int)(p & (HW - 1));      // p % HW
    const float* base = logits + (size_t)b * NUM_C * HW + hw;

    // Load 19 float4 (fully coalesced per class, high MLP).
    float a0[NUM_C], a1[NUM_C], a2[NUM_C], a3[NUM_C];
#pragma unroll
    for (int c = 0; c < NUM_C; c++) {
        float4 v = *reinterpret_cast<const float4*>(base + (size_t)c * HW);
        a0[c] = v.x; a1[c] = v.y; a2[c] = v.z; a3[c] = v.w;
    }

    // Targets are int32 (JAX x64 disabled downgrades int64 -> int32).
    int4 tv = *reinterpret_cast<const int4*>(targets + p);

    float ce_local = 0.f;
    unsigned nv_local = 0u;

    process_pixel(a0, tv.x, ce_local, nv_local, s_sum, s_cnt);
    process_pixel(a1, tv.y, ce_local, nv_local, s_sum, s_cnt);
    process_pixel(a2, tv.z, ce_local, nv_local, s_sum, s_cnt);
    process_pixel(a3, tv.w, ce_local, nv_local, s_sum, s_cnt);

    // Warp-level reduction of ce / n_valid, then one shared atomic per warp.
#pragma unroll
    for (int o = 16; o > 0; o >>= 1) {
        ce_local += __shfl_down_sync(0xffffffffu, ce_local, o);
        nv_local += __shfl_down_sync(0xffffffffu, nv_local, o);
    }
    if ((tid & 31) == 0) {
        atomicAdd(&s_ce, ce_local);
        atomicAdd(&s_nv, nv_local);
    }
    __syncthreads();

    // Per-block flush to global accumulators (double for stable replays).
    if (tid < NUM_C) {
        atomicAdd(&g_csum[tid], (double)s_sum[tid]);
        atomicAdd(&g_ccnt[tid], (unsigned long long)s_cnt[tid]);
    }
    if (tid == 32) {
        atomicAdd(&g_ce, (double)s_ce);
        atomicAdd(&g_nv, (unsigned long long)s_nv);
    }
}

__global__ void cepf_final_kernel(float* __restrict__ out) {
    if (threadIdx.x == 0 && blockIdx.x == 0) {
        unsigned long long nv = g_nv;
        double ce = g_ce / (double)(nv > 0ULL ? nv : 1ULL);
        double fsum = 0.0;
        int npresent = 0;
        for (int c = 0; c < NUM_C; c++) {
            unsigned long long cnt = g_ccnt[c];
            if (cnt > 0ULL) {
                fsum += g_csum[c] / (double)cnt;
                npresent++;
            }
        }
        double focal = fsum / (double)(npresent > 0 ? npresent : 1);
        out[0] = (float)(ce + focal);
    }
}

extern "C" void kernel_launch(void* const* d_in, const int* in_sizes, int n_in,
                              void* d_out, int out_size) {
    const float* logits = (const float*)d_in[0];
    const int* targets = (const int*)d_in[1];
    float* out = (float*)d_out;

    cepf_init_kernel<<<1, 32>>>();

    // NPIX / 4 pixels-per-thread / 256 threads-per-block = 2048 blocks (exact)
    int blocks = NPIX / (4 * 256);
    cepf_main_kernel<<<blocks, 256>>>(logits, targets);

    cepf_final_kernel<<<1, 32>>>(out);
}